// round 13
// baseline (speedup 1.0000x reference)
#include <cuda_runtime.h>
#include <cuda_fp16.h>
#include <cstdint>

#define NROWS 100000
#define D     128
#define PP    8192
#define NEG   256
#define TEMPF 0.07f
#define NTILES 782          // ceil(100000/128)

// Scratch (device globals: allocation-free per harness rules)
__device__ __align__(16) __half  g_embh [ (size_t)NROWS * D ];  // fp16 projected embeddings
__device__ __align__(16) int8_t  g_embi8[ (size_t)NROWS * D ];  // int8 quantized rows
__device__ unsigned g_gmax_bits;                                // global |emb| max (float bits)
__device__ float g_losses[2 * PP];

// ---------------------------------------------------------------------------
// Kernel 0: reset global max (graph replays must be deterministic)
// ---------------------------------------------------------------------------
__global__ void init_kernel() { g_gmax_bits = 0u; }

// ---------------------------------------------------------------------------
// Kernel 1: embh = fp16(X @ W^T + b) — persistent cp.async-pipelined HMMA.
// Epilogue folds the global |emb| max via REDUX + atomicMax (int-punned
// non-negative float: exact, order-independent).
// ---------------------------------------------------------------------------
#define WPITCH 272
#define WBYTES (128 * WPITCH)
#define XFP    136
#define XPB    (XFP * 4)
#define XBUFB  (128 * XPB)
#define SM_W   0
#define SM_B   WBYTES
#define SM_X0  (WBYTES + 512)
#define SM_X1  (SM_X0 + XBUFB)
#define GEMM_SMEM (SM_X1 + XBUFB)        // 174592 B

#define LDSM4(d, addr) \
    asm volatile("ldmatrix.sync.aligned.m8n8.x4.shared.b16 {%0,%1,%2,%3}, [%4];" \
        : "=r"((d)[0]), "=r"((d)[1]), "=r"((d)[2]), "=r"((d)[3]) : "r"(addr))

#define MMA16816(c, a, b0, b1) \
    asm volatile("mma.sync.aligned.m16n8k16.row.col.f32.f16.f16.f32 " \
        "{%0,%1,%2,%3},{%4,%5,%6,%7},{%8,%9},{%0,%1,%2,%3};" \
        : "+f"((c)[0]), "+f"((c)[1]), "+f"((c)[2]), "+f"((c)[3]) \
        : "r"((a)[0]), "r"((a)[1]), "r"((a)[2]), "r"((a)[3]), "r"(b0), "r"(b1))

#define CP16(dst, src) \
    asm volatile("cp.async.cg.shared.global [%0], [%1], 16;" :: "r"(dst), "l"(src))

__device__ __forceinline__ uint32_t packh2(float lo, float hi) {
    __half2 h = __floats2half2_rn(lo, hi);
    return *(uint32_t*)&h;
}

__global__ void __launch_bounds__(512, 1) gemm_kernel(const float* __restrict__ X,
                                                      const float* __restrict__ W,
                                                      const float* __restrict__ b) {
    extern __shared__ char sh[];
    float* bsm = (float*)(sh + SM_B);

    int tid  = threadIdx.x;
    int lane = tid & 31;
    int warp = tid >> 5;

    for (int i = tid; i < 128 * 32; i += 512) {
        int rr = i >> 5, c4 = i & 31;
        float4 v = __ldg((const float4*)(W + (size_t)rr * D) + c4);
        *(uint2*)(sh + SM_W + rr * WPITCH + c4 * 8) =
            make_uint2(packh2(v.x, v.y), packh2(v.z, v.w));
    }
    if (tid < D) bsm[tid] = b[tid];

    uint32_t wsh_u = (uint32_t)__cvta_generic_to_shared(sh + SM_W);
    uint32_t x0_u  = (uint32_t)__cvta_generic_to_shared(sh + SM_X0);

    int wm = warp >> 2;
    int wn = warp & 3;
    int n_b = wn * 32;

    int q = lane >> 3;
    int r = lane & 7;
    int g = lane >> 2;
    int t = lane & 3;

    uint32_t bBase = wsh_u + (uint32_t)((n_b + (q >> 1) * 8 + r) * WPITCH + (q & 1) * 16);

    auto issue_x = [&](uint32_t xbuf, int tile) {
        int row0 = tile * 128;
#pragma unroll
        for (int it = 0; it < 8; it++) {
            int idx = it * 512 + tid;
            int rr = idx >> 5, cc = idx & 31;
            int gr = row0 + rr;
            if (gr >= NROWS) gr = NROWS - 1;
            const float* src = X + (size_t)gr * D + cc * 4;
            CP16(xbuf + rr * XPB + cc * 16, src);
        }
    };

    int t0 = blockIdx.x;
    if (t0 < NTILES) issue_x(x0_u, t0);
    asm volatile("cp.async.commit_group;" ::: "memory");
    __syncthreads();

    int bufsel = 0;
    for (int tile = t0; tile < NTILES; tile += 148) {
        uint32_t xcur = bufsel ? (x0_u + XBUFB) : x0_u;
        uint32_t xnxt = bufsel ? x0_u : (x0_u + XBUFB);

        int tn = tile + 148;
        if (tn < NTILES) issue_x(xnxt, tn);
        asm volatile("cp.async.commit_group;" ::: "memory");
        asm volatile("cp.async.wait_group 1;" ::: "memory");
        __syncthreads();

        const float* Xb = (const float*)(sh + (xcur - (uint32_t)__cvta_generic_to_shared(sh)));
        float acc[2][4][4];
#pragma unroll
        for (int mt = 0; mt < 2; mt++)
#pragma unroll
            for (int nt = 0; nt < 4; nt++)
#pragma unroll
                for (int j = 0; j < 4; j++) acc[mt][nt][j] = 0.f;

        int m_b = wm * 32;
#pragma unroll
        for (int ks = 0; ks < 8; ks++) {
            uint32_t A[2][4], B[2][4];
#pragma unroll
            for (int mt = 0; mt < 2; mt++) {
                const float* p0 = Xb + (m_b + mt * 16 + g) * XFP + ks * 16 + 2 * t;
                const float* p1 = p0 + 8 * XFP;
                float2 v0 = *(const float2*)p0;
                float2 v1 = *(const float2*)p1;
                float2 v2 = *(const float2*)(p0 + 8);
                float2 v3 = *(const float2*)(p1 + 8);
                A[mt][0] = packh2(v0.x, v0.y);
                A[mt][1] = packh2(v1.x, v1.y);
                A[mt][2] = packh2(v2.x, v2.y);
                A[mt][3] = packh2(v3.x, v3.y);
            }
#pragma unroll
            for (int np = 0; np < 2; np++)
                LDSM4(B[np], bBase + np * 16 * WPITCH + ks * 32);
#pragma unroll
            for (int mt = 0; mt < 2; mt++)
#pragma unroll
                for (int nt = 0; nt < 4; nt++)
                    MMA16816(acc[mt][nt], A[mt],
                             B[nt >> 1][(nt & 1) * 2], B[nt >> 1][(nt & 1) * 2 + 1]);
        }

        int row0 = tile * 128;
        float tmax = 0.f;
#pragma unroll
        for (int nt = 0; nt < 4; nt++) {
            int col = n_b + nt * 8 + 2 * t;
            float2 bb = *(float2*)(bsm + col);
#pragma unroll
            for (int mt = 0; mt < 2; mt++) {
                int rA = row0 + m_b + mt * 16 + g;
                int rB = rA + 8;
                float e0 = acc[mt][nt][0] + bb.x;
                float e1 = acc[mt][nt][1] + bb.y;
                float e2 = acc[mt][nt][2] + bb.x;
                float e3 = acc[mt][nt][3] + bb.y;
                tmax = fmaxf(tmax, fmaxf(fmaxf(fabsf(e0), fabsf(e1)),
                                         fmaxf(fabsf(e2), fabsf(e3))));
                if (rA < NROWS)
                    *(__half2*)(g_embh + (size_t)rA * D + col) = __floats2half2_rn(e0, e1);
                if (rB < NROWS)
                    *(__half2*)(g_embh + (size_t)rB * D + col) = __floats2half2_rn(e2, e3);
            }
        }
        unsigned um = __reduce_max_sync(0xffffffffu, __float_as_uint(tmax));
        if (lane == 0) atomicMax(&g_gmax_bits, um);

        __syncthreads();
        bufsel ^= 1;
    }
}

// ---------------------------------------------------------------------------
// Kernel 1b: int8 quantization with one GLOBAL scale (streaming convert).
// ---------------------------------------------------------------------------
__global__ void __launch_bounds__(256) quant_kernel() {
    float gmax = __uint_as_float(g_gmax_bits);
    float inv  = 127.f / fmaxf(gmax, 1e-20f);

    size_t idx = (size_t)(blockIdx.x * 256 + threadIdx.x) * 8;
    uint4 v = *(const uint4*)(g_embh + idx);
    const __half2* h2 = (const __half2*)&v;
    int qi[8];
#pragma unroll
    for (int j = 0; j < 4; j++) {
        float2 f = __half22float2(h2[j]);
        qi[2 * j]     = max(-127, min(127, __float2int_rn(f.x * inv)));
        qi[2 * j + 1] = max(-127, min(127, __float2int_rn(f.y * inv)));
    }
    uint32_t p0 = (uint32_t)(qi[0] & 0xFF) | ((uint32_t)(qi[1] & 0xFF) << 8) |
                  ((uint32_t)(qi[2] & 0xFF) << 16) | ((uint32_t)(qi[3] & 0xFF) << 24);
    uint32_t p1 = (uint32_t)(qi[4] & 0xFF) | ((uint32_t)(qi[5] & 0xFF) << 8) |
                  ((uint32_t)(qi[6] & 0xFF) << 16) | ((uint32_t)(qi[7] & 0xFF) << 24);
    *(uint2*)(g_embi8 + idx) = make_uint2(p0, p1);
}

// ---------------------------------------------------------------------------
// Kernel 2: per (p, branch): logits, logsumexp, per-pair loss.
// Negatives: coalesced 8-lane/row gathers (1 L1 line per row, the wavefront
// floor), ALL 8 row loads batched upfront (MLP=8), dp4a exact dot + REDUX.
// ---------------------------------------------------------------------------
__global__ void branch_kernel(const int* __restrict__ pos_anchor,
                              const int* __restrict__ pos_partner,
                              const int* __restrict__ neg_idx,
                              const int* __restrict__ weak_anchor,
                              const int* __restrict__ weak_partner,
                              const int* __restrict__ weak_neg_idx) {
    __shared__ float qsh[D], ksh[D];
    __shared__ int   sidx[NEG];
    __shared__ float sdots[NEG + 1];
    __shared__ uint32_t qi8[32];
    __shared__ float sred[9];

    int p  = blockIdx.x;
    int br = blockIdx.y;
    const int* anc = br ? weak_anchor  : pos_anchor;
    const int* par = br ? weak_partner : pos_partner;
    const int* nix = br ? weak_neg_idx : neg_idx;

    int tid  = threadIdx.x;
    int lane = tid & 31;
    int warp = tid >> 5;

    int a  = anc[p];
    int pr = par[p];
    if (tid < D) qsh[tid]     = __half2float(g_embh[(size_t)a  * D + tid]);
    else         ksh[tid - D] = __half2float(g_embh[(size_t)pr * D + (tid - D)]);
    sidx[tid] = nix[(size_t)p * NEG + tid];
    if (tid < 32) qi8[tid] = ((const uint32_t*)(g_embi8 + (size_t)a * D))[tid];
    __syncthreads();

    float gmax = __uint_as_float(g_gmax_bits);
    float gsc  = gmax * (1.f / 127.f);
    float gs2  = gsc * gsc;

    int grp = lane >> 3;            // 0..3: negative within quad
    int gl  = lane & 7;             // lane within 8-lane group (16B of the row)
    uint32_t gmask = 0xFFu << (grp * 8);

    uint32_t qp[4];
#pragma unroll
    for (int j = 0; j < 4; j++) qp[j] = qi8[gl * 4 + j];

    // positive dot (warp 0, fp16-accuracy path)
    if (warp == 0) {
        float s = 0.f;
#pragma unroll
        for (int j = 0; j < 4; j++) s += qsh[lane * 4 + j] * ksh[lane * 4 + j];
#pragma unroll
        for (int m = 16; m >= 1; m >>= 1) s += __shfl_xor_sync(0xffffffffu, s, m);
        if (lane == 0) sdots[NEG] = s;
    }

    // 32 negatives per warp: all 8 coalesced row-gathers issued upfront (MLP=8)
    {
        int nbase = warp * 32 + grp;
        const int8_t* base = g_embi8 + (gl << 4);
        uint4 v[8];
#pragma unroll
        for (int it = 0; it < 8; it++)
            v[it] = *(const uint4*)(base + ((size_t)sidx[nbase + it * 4] << 7));

#pragma unroll
        for (int it = 0; it < 8; it++) {
            int isum = 0;
            isum = __dp4a((int)v[it].x, (int)qp[0], isum);
            isum = __dp4a((int)v[it].y, (int)qp[1], isum);
            isum = __dp4a((int)v[it].z, (int)qp[2], isum);
            isum = __dp4a((int)v[it].w, (int)qp[3], isum);
            isum = __reduce_add_sync(gmask, isum);
            if (gl == 0) sdots[nbase + it * 4] = (float)isum * gs2;
        }
    }
    __syncthreads();

    const float invT = 1.0f / TEMPF;

    float v = sdots[tid];
    float mv = (tid == 0) ? fmaxf(v, sdots[NEG]) : v;
#pragma unroll
    for (int m = 16; m >= 1; m >>= 1) mv = fmaxf(mv, __shfl_xor_sync(0xffffffffu, mv, m));
    if (lane == 0) sred[warp] = mv;
    __syncthreads();
    if (tid == 0) {
        float m2 = sred[0];
#pragma unroll
        for (int i = 1; i < 8; i++) m2 = fmaxf(m2, sred[i]);
        sred[8] = m2;
    }
    __syncthreads();
    float ml = sred[8] * invT;

    float e = expf(v * invT - ml);
    if (tid == 0) e += expf(sdots[NEG] * invT - ml);
#pragma unroll
    for (int m = 16; m >= 1; m >>= 1) e += __shfl_xor_sync(0xffffffffu, e, m);
    if (lane == 0) sred[warp] = e;
    __syncthreads();
    if (tid == 0) {
        float s = 0.f;
#pragma unroll
        for (int i = 0; i < 8; i++) s += sred[i];
        g_losses[br * PP + p] = ml + logf(s) - sdots[NEG] * invT;
    }
}

// ---------------------------------------------------------------------------
// Kernel 3: deterministic mean reduction (1024 threads, MLP-overlapped)
// ---------------------------------------------------------------------------
__global__ void __launch_bounds__(1024) finalize_kernel(float* __restrict__ out) {
    __shared__ double s0sh[1024], s1sh[1024];
    int tid = threadIdx.x;
    double s0 = 0.0, s1 = 0.0;
#pragma unroll
    for (int i = 0; i < PP / 1024; i++) {
        s0 += (double)g_losses[i * 1024 + tid];
        s1 += (double)g_losses[PP + i * 1024 + tid];
    }
    s0sh[tid] = s0; s1sh[tid] = s1;
    __syncthreads();
    for (int st = 512; st > 0; st >>= 1) {
        if (tid < st) { s0sh[tid] += s0sh[tid + st]; s1sh[tid] += s1sh[tid + st]; }
        __syncthreads();
    }
    if (tid == 0)
        out[0] = (float)(s0sh[0] / (double)PP + 0.1 * (s1sh[0] / (double)PP));
}

extern "C" void kernel_launch(void* const* d_in, const int* in_sizes, int n_in,
                              void* d_out, int out_size) {
    const float* X  = (const float*)d_in[0];
    const float* W  = (const float*)d_in[1];
    const float* b  = (const float*)d_in[2];
    const int*   pa = (const int*)d_in[3];
    const int*   pp = (const int*)d_in[4];
    const int*   ni = (const int*)d_in[5];
    const int*   wa = (const int*)d_in[6];
    const int*   wp = (const int*)d_in[7];
    const int*   wn = (const int*)d_in[8];
    float* out = (float*)d_out;

    cudaFuncSetAttribute(gemm_kernel, cudaFuncAttributeMaxDynamicSharedMemorySize, GEMM_SMEM);

    init_kernel<<<1, 1>>>();
    gemm_kernel<<<148, 512, GEMM_SMEM>>>(X, W, b);
    quant_kernel<<<(NROWS * D / 8) / 256, 256>>>();   // 6250 blocks exact
    branch_kernel<<<dim3(PP, 2), 256>>>(pa, pp, ni, wa, wp, wn);
    finalize_kernel<<<1, 1024>>>(out);
}

// round 14
// speedup vs baseline: 1.0835x; 1.0835x over previous
#include <cuda_runtime.h>
#include <cuda_fp16.h>
#include <cstdint>

#define NROWS 100000
#define D     128
#define PP    8192
#define NEG   256
#define TEMPF 0.07f
#define NTILES 782          // ceil(100000/128)

// Scratch (device globals: allocation-free per harness rules)
__device__ __align__(16) __half  g_embh [ (size_t)NROWS * D ];  // fp16 projected embeddings
__device__ __align__(16) int8_t  g_embi8[ (size_t)NROWS * D ];  // int8 quantized rows
__device__ unsigned g_gmax_bits;                                // global |emb| max (float bits)
__device__ float g_losses[2 * PP];

// ---------------------------------------------------------------------------
// Kernel 0: reset global max (graph replays must be deterministic)
// ---------------------------------------------------------------------------
__global__ void init_kernel() { g_gmax_bits = 0u; }

// ---------------------------------------------------------------------------
// Kernel 1: embh = fp16(X @ W^T + b) — persistent cp.async-pipelined HMMA.
// Epilogue folds the global |emb| max via REDUX + atomicMax.
// ---------------------------------------------------------------------------
#define WPITCH 272
#define WBYTES (128 * WPITCH)
#define XFP    136
#define XPB    (XFP * 4)
#define XBUFB  (128 * XPB)
#define SM_W   0
#define SM_B   WBYTES
#define SM_X0  (WBYTES + 512)
#define SM_X1  (SM_X0 + XBUFB)
#define GEMM_SMEM (SM_X1 + XBUFB)        // 174592 B

#define LDSM4(d, addr) \
    asm volatile("ldmatrix.sync.aligned.m8n8.x4.shared.b16 {%0,%1,%2,%3}, [%4];" \
        : "=r"((d)[0]), "=r"((d)[1]), "=r"((d)[2]), "=r"((d)[3]) : "r"(addr))

#define MMA16816(c, a, b0, b1) \
    asm volatile("mma.sync.aligned.m16n8k16.row.col.f32.f16.f16.f32 " \
        "{%0,%1,%2,%3},{%4,%5,%6,%7},{%8,%9},{%0,%1,%2,%3};" \
        : "+f"((c)[0]), "+f"((c)[1]), "+f"((c)[2]), "+f"((c)[3]) \
        : "r"((a)[0]), "r"((a)[1]), "r"((a)[2]), "r"((a)[3]), "r"(b0), "r"(b1))

#define CP16(dst, src) \
    asm volatile("cp.async.cg.shared.global [%0], [%1], 16;" :: "r"(dst), "l"(src))

__device__ __forceinline__ uint32_t packh2(float lo, float hi) {
    __half2 h = __floats2half2_rn(lo, hi);
    return *(uint32_t*)&h;
}

__global__ void __launch_bounds__(512, 1) gemm_kernel(const float* __restrict__ X,
                                                      const float* __restrict__ W,
                                                      const float* __restrict__ b) {
    extern __shared__ char sh[];
    float* bsm = (float*)(sh + SM_B);

    int tid  = threadIdx.x;
    int lane = tid & 31;
    int warp = tid >> 5;

    for (int i = tid; i < 128 * 32; i += 512) {
        int rr = i >> 5, c4 = i & 31;
        float4 v = __ldg((const float4*)(W + (size_t)rr * D) + c4);
        *(uint2*)(sh + SM_W + rr * WPITCH + c4 * 8) =
            make_uint2(packh2(v.x, v.y), packh2(v.z, v.w));
    }
    if (tid < D) bsm[tid] = b[tid];

    uint32_t wsh_u = (uint32_t)__cvta_generic_to_shared(sh + SM_W);
    uint32_t x0_u  = (uint32_t)__cvta_generic_to_shared(sh + SM_X0);

    int wm = warp >> 2;
    int wn = warp & 3;
    int n_b = wn * 32;

    int q = lane >> 3;
    int r = lane & 7;
    int g = lane >> 2;
    int t = lane & 3;

    uint32_t bBase = wsh_u + (uint32_t)((n_b + (q >> 1) * 8 + r) * WPITCH + (q & 1) * 16);

    auto issue_x = [&](uint32_t xbuf, int tile) {
        int row0 = tile * 128;
#pragma unroll
        for (int it = 0; it < 8; it++) {
            int idx = it * 512 + tid;
            int rr = idx >> 5, cc = idx & 31;
            int gr = row0 + rr;
            if (gr >= NROWS) gr = NROWS - 1;
            const float* src = X + (size_t)gr * D + cc * 4;
            CP16(xbuf + rr * XPB + cc * 16, src);
        }
    };

    int t0 = blockIdx.x;
    if (t0 < NTILES) issue_x(x0_u, t0);
    asm volatile("cp.async.commit_group;" ::: "memory");
    __syncthreads();

    int bufsel = 0;
    for (int tile = t0; tile < NTILES; tile += 148) {
        uint32_t xcur = bufsel ? (x0_u + XBUFB) : x0_u;
        uint32_t xnxt = bufsel ? x0_u : (x0_u + XBUFB);

        int tn = tile + 148;
        if (tn < NTILES) issue_x(xnxt, tn);
        asm volatile("cp.async.commit_group;" ::: "memory");
        asm volatile("cp.async.wait_group 1;" ::: "memory");
        __syncthreads();

        const float* Xb = (const float*)(sh + (xcur - (uint32_t)__cvta_generic_to_shared(sh)));
        float acc[2][4][4];
#pragma unroll
        for (int mt = 0; mt < 2; mt++)
#pragma unroll
            for (int nt = 0; nt < 4; nt++)
#pragma unroll
                for (int j = 0; j < 4; j++) acc[mt][nt][j] = 0.f;

        int m_b = wm * 32;
#pragma unroll
        for (int ks = 0; ks < 8; ks++) {
            uint32_t A[2][4], B[2][4];
#pragma unroll
            for (int mt = 0; mt < 2; mt++) {
                const float* p0 = Xb + (m_b + mt * 16 + g) * XFP + ks * 16 + 2 * t;
                const float* p1 = p0 + 8 * XFP;
                float2 v0 = *(const float2*)p0;
                float2 v1 = *(const float2*)p1;
                float2 v2 = *(const float2*)(p0 + 8);
                float2 v3 = *(const float2*)(p1 + 8);
                A[mt][0] = packh2(v0.x, v0.y);
                A[mt][1] = packh2(v1.x, v1.y);
                A[mt][2] = packh2(v2.x, v2.y);
                A[mt][3] = packh2(v3.x, v3.y);
            }
#pragma unroll
            for (int np = 0; np < 2; np++)
                LDSM4(B[np], bBase + np * 16 * WPITCH + ks * 32);
#pragma unroll
            for (int mt = 0; mt < 2; mt++)
#pragma unroll
                for (int nt = 0; nt < 4; nt++)
                    MMA16816(acc[mt][nt], A[mt],
                             B[nt >> 1][(nt & 1) * 2], B[nt >> 1][(nt & 1) * 2 + 1]);
        }

        int row0 = tile * 128;
        float tmax = 0.f;
#pragma unroll
        for (int nt = 0; nt < 4; nt++) {
            int col = n_b + nt * 8 + 2 * t;
            float2 bb = *(float2*)(bsm + col);
#pragma unroll
            for (int mt = 0; mt < 2; mt++) {
                int rA = row0 + m_b + mt * 16 + g;
                int rB = rA + 8;
                float e0 = acc[mt][nt][0] + bb.x;
                float e1 = acc[mt][nt][1] + bb.y;
                float e2 = acc[mt][nt][2] + bb.x;
                float e3 = acc[mt][nt][3] + bb.y;
                tmax = fmaxf(tmax, fmaxf(fmaxf(fabsf(e0), fabsf(e1)),
                                         fmaxf(fabsf(e2), fabsf(e3))));
                if (rA < NROWS)
                    *(__half2*)(g_embh + (size_t)rA * D + col) = __floats2half2_rn(e0, e1);
                if (rB < NROWS)
                    *(__half2*)(g_embh + (size_t)rB * D + col) = __floats2half2_rn(e2, e3);
            }
        }
        unsigned um = __reduce_max_sync(0xffffffffu, __float_as_uint(tmax));
        if (lane == 0) atomicMax(&g_gmax_bits, um);

        __syncthreads();
        bufsel ^= 1;
    }
}

// ---------------------------------------------------------------------------
// Kernel 1b: int8 quantization with one GLOBAL scale (streaming convert).
// ---------------------------------------------------------------------------
__global__ void __launch_bounds__(256) quant_kernel() {
    float gmax = __uint_as_float(g_gmax_bits);
    float inv  = 127.f / fmaxf(gmax, 1e-20f);

    size_t idx = (size_t)(blockIdx.x * 256 + threadIdx.x) * 8;
    uint4 v = *(const uint4*)(g_embh + idx);
    const __half2* h2 = (const __half2*)&v;
    int qi[8];
#pragma unroll
    for (int j = 0; j < 4; j++) {
        float2 f = __half22float2(h2[j]);
        qi[2 * j]     = max(-127, min(127, __float2int_rn(f.x * inv)));
        qi[2 * j + 1] = max(-127, min(127, __float2int_rn(f.y * inv)));
    }
    uint32_t p0 = (uint32_t)(qi[0] & 0xFF) | ((uint32_t)(qi[1] & 0xFF) << 8) |
                  ((uint32_t)(qi[2] & 0xFF) << 16) | ((uint32_t)(qi[3] & 0xFF) << 24);
    uint32_t p1 = (uint32_t)(qi[4] & 0xFF) | ((uint32_t)(qi[5] & 0xFF) << 8) |
                  ((uint32_t)(qi[6] & 0xFF) << 16) | ((uint32_t)(qi[7] & 0xFF) << 24);
    *(uint2*)(g_embi8 + idx) = make_uint2(p0, p1);
}

// ---------------------------------------------------------------------------
// Kernel 2: WARP-PER-PAIR. One warp owns one (p, branch): 256 negatives in
// 64 unrolled iterations (4 negatives/iter, 8 coalesced lanes/row = L1-line
// floor), dots kept in registers, warp-local logsumexp with __expf/__logf.
// NO block barriers, no dot smem.
// ---------------------------------------------------------------------------
__global__ void __launch_bounds__(256) branch_kernel(
                              const int* __restrict__ pos_anchor,
                              const int* __restrict__ pos_partner,
                              const int* __restrict__ neg_idx,
                              const int* __restrict__ weak_anchor,
                              const int* __restrict__ weak_partner,
                              const int* __restrict__ weak_neg_idx) {
    __shared__ int sidx[8][NEG];    // per-warp index staging (8 KB)

    int tid  = threadIdx.x;
    int lane = tid & 31;
    int warp = tid >> 5;

    int p  = blockIdx.x * 8 + warp;
    int br = blockIdx.y;
    const int* anc = br ? weak_anchor  : pos_anchor;
    const int* par = br ? weak_partner : pos_partner;
    const int* nix = br ? weak_neg_idx : neg_idx;

    int a  = anc[p];                // warp-broadcast loads
    int pr = par[p];

    // stage this warp's 256 indices (2x LDG.128 per lane)
    {
        const int4* np4 = (const int4*)(nix + (size_t)p * NEG);
        int4 i0 = np4[lane];
        int4 i1 = np4[lane + 32];
        ((int4*)sidx[warp])[lane]      = i0;
        ((int4*)sidx[warp])[lane + 32] = i1;
    }

    // q int8 row -> per-lane 16B chunk via shfl
    int gl  = lane & 7;             // lane within 8-lane row group
    int grp = lane >> 3;            // which negative of the quad
    uint32_t qrow = ((const uint32_t*)(g_embi8 + (size_t)a * D))[lane];
    uint32_t qp[4];
#pragma unroll
    for (int j = 0; j < 4; j++)
        qp[j] = __shfl_sync(0xffffffffu, qrow, gl * 4 + j);

    // positive dot (fp16-accuracy path): 4 halves per lane
    float pos;
    {
        uint2 qh = ((const uint2*)(g_embh + (size_t)a  * D))[lane];
        uint2 kh = ((const uint2*)(g_embh + (size_t)pr * D))[lane];
        __half2 q0 = *(__half2*)&qh.x, q1 = *(__half2*)&qh.y;
        __half2 k0 = *(__half2*)&kh.x, k1 = *(__half2*)&kh.y;
        float2 fq0 = __half22float2(q0), fq1 = __half22float2(q1);
        float2 fk0 = __half22float2(k0), fk1 = __half22float2(k1);
        float s = fq0.x * fk0.x + fq0.y * fk0.y + fq1.x * fk1.x + fq1.y * fk1.y;
#pragma unroll
        for (int m = 16; m >= 1; m >>= 1) s += __shfl_xor_sync(0xffffffffu, s, m);
        pos = s;
    }

    float gmax = __uint_as_float(g_gmax_bits);
    float gsc  = gmax * (1.f / 127.f);
    float gs2  = gsc * gsc;

    __syncwarp();                   // sidx smem visible to warp

    // 64 iterations x 4 negatives; dots land in registers
    uint32_t gmask = 0xFFu << (grp * 8);
    const int8_t* gbase = g_embi8 + (gl << 4);
    const int* sw = sidx[warp] + grp;
    float dots[8];
#pragma unroll
    for (int it = 0; it < 64; it++) {
        int idx = sw[it * 4];                       // LDS, immediate offset
        uint4 v = *(const uint4*)(gbase + ((size_t)idx << 7));
        int isum = 0;
        isum = __dp4a((int)v.x, (int)qp[0], isum);
        isum = __dp4a((int)v.y, (int)qp[1], isum);
        isum = __dp4a((int)v.z, (int)qp[2], isum);
        isum = __dp4a((int)v.w, (int)qp[3], isum);
        isum = __reduce_add_sync(gmask, isum);
        if ((it & 7) == gl) dots[it >> 3] = (float)isum * gs2;
    }

    // warp-local logsumexp over 257 logits
    const float invT = 1.0f / TEMPF;
    float mv = pos;
#pragma unroll
    for (int k = 0; k < 8; k++) mv = fmaxf(mv, dots[k]);
#pragma unroll
    for (int m = 16; m >= 1; m >>= 1) mv = fmaxf(mv, __shfl_xor_sync(0xffffffffu, mv, m));
    float ml = mv * invT;

    float e = 0.f;
#pragma unroll
    for (int k = 0; k < 8; k++) e += __expf(dots[k] * invT - ml);
#pragma unroll
    for (int m = 16; m >= 1; m >>= 1) e += __shfl_xor_sync(0xffffffffu, e, m);

    if (lane == 0) {
        float total = e + __expf(pos * invT - ml);
        g_losses[br * PP + p] = ml + __logf(total) - pos * invT;
    }
}

// ---------------------------------------------------------------------------
// Kernel 3: deterministic mean reduction (1024 threads, MLP-overlapped)
// ---------------------------------------------------------------------------
__global__ void __launch_bounds__(1024) finalize_kernel(float* __restrict__ out) {
    __shared__ double s0sh[1024], s1sh[1024];
    int tid = threadIdx.x;
    double s0 = 0.0, s1 = 0.0;
#pragma unroll
    for (int i = 0; i < PP / 1024; i++) {
        s0 += (double)g_losses[i * 1024 + tid];
        s1 += (double)g_losses[PP + i * 1024 + tid];
    }
    s0sh[tid] = s0; s1sh[tid] = s1;
    __syncthreads();
    for (int st = 512; st > 0; st >>= 1) {
        if (tid < st) { s0sh[tid] += s0sh[tid + st]; s1sh[tid] += s1sh[tid + st]; }
        __syncthreads();
    }
    if (tid == 0)
        out[0] = (float)(s0sh[0] / (double)PP + 0.1 * (s1sh[0] / (double)PP));
}

extern "C" void kernel_launch(void* const* d_in, const int* in_sizes, int n_in,
                              void* d_out, int out_size) {
    const float* X  = (const float*)d_in[0];
    const float* W  = (const float*)d_in[1];
    const float* b  = (const float*)d_in[2];
    const int*   pa = (const int*)d_in[3];
    const int*   pp = (const int*)d_in[4];
    const int*   ni = (const int*)d_in[5];
    const int*   wa = (const int*)d_in[6];
    const int*   wp = (const int*)d_in[7];
    const int*   wn = (const int*)d_in[8];
    float* out = (float*)d_out;

    cudaFuncSetAttribute(gemm_kernel, cudaFuncAttributeMaxDynamicSharedMemorySize, GEMM_SMEM);

    init_kernel<<<1, 1>>>();
    gemm_kernel<<<148, 512, GEMM_SMEM>>>(X, W, b);
    quant_kernel<<<(NROWS * D / 8) / 256, 256>>>();   // 6250 blocks exact
    branch_kernel<<<dim3(PP / 8, 2), 256>>>(pa, pp, ni, wa, wp, wn);
    finalize_kernel<<<1, 1024>>>(out);
}

// round 15
// speedup vs baseline: 1.2228x; 1.1286x over previous
#include <cuda_runtime.h>
#include <cuda_fp16.h>
#include <cstdint>

#define NROWS 100000
#define D     128
#define PP    8192
#define NEG   256
#define TEMPF 0.07f
#define NTILES 782          // ceil(100000/128)

// Scratch (device globals: allocation-free per harness rules)
__device__ __align__(16) __half  g_embh [ (size_t)NROWS * D ];  // fp16 projected embeddings
__device__ __align__(16) int8_t  g_embi8[ (size_t)NROWS * D ];  // int8 quantized rows
__device__ unsigned g_gmax_bits;                                // global |emb| max (float bits)
__device__ float g_losses[2 * PP];

// ---------------------------------------------------------------------------
// Kernel 0: reset global max (graph replays must be deterministic)
// ---------------------------------------------------------------------------
__global__ void init_kernel() { g_gmax_bits = 0u; }

// ---------------------------------------------------------------------------
// Kernel 1: embh = fp16(X @ W^T + b) — persistent cp.async-pipelined HMMA.
// Epilogue folds the global |emb| max via REDUX + atomicMax.
// ---------------------------------------------------------------------------
#define WPITCH 272
#define WBYTES (128 * WPITCH)
#define XFP    136
#define XPB    (XFP * 4)
#define XBUFB  (128 * XPB)
#define SM_W   0
#define SM_B   WBYTES
#define SM_X0  (WBYTES + 512)
#define SM_X1  (SM_X0 + XBUFB)
#define GEMM_SMEM (SM_X1 + XBUFB)        // 174592 B

#define LDSM4(d, addr) \
    asm volatile("ldmatrix.sync.aligned.m8n8.x4.shared.b16 {%0,%1,%2,%3}, [%4];" \
        : "=r"((d)[0]), "=r"((d)[1]), "=r"((d)[2]), "=r"((d)[3]) : "r"(addr))

#define MMA16816(c, a, b0, b1) \
    asm volatile("mma.sync.aligned.m16n8k16.row.col.f32.f16.f16.f32 " \
        "{%0,%1,%2,%3},{%4,%5,%6,%7},{%8,%9},{%0,%1,%2,%3};" \
        : "+f"((c)[0]), "+f"((c)[1]), "+f"((c)[2]), "+f"((c)[3]) \
        : "r"((a)[0]), "r"((a)[1]), "r"((a)[2]), "r"((a)[3]), "r"(b0), "r"(b1))

#define CP16(dst, src) \
    asm volatile("cp.async.cg.shared.global [%0], [%1], 16;" :: "r"(dst), "l"(src))

__device__ __forceinline__ uint32_t packh2(float lo, float hi) {
    __half2 h = __floats2half2_rn(lo, hi);
    return *(uint32_t*)&h;
}

__global__ void __launch_bounds__(512, 1) gemm_kernel(const float* __restrict__ X,
                                                      const float* __restrict__ W,
                                                      const float* __restrict__ b) {
    extern __shared__ char sh[];
    float* bsm = (float*)(sh + SM_B);

    int tid  = threadIdx.x;
    int lane = tid & 31;
    int warp = tid >> 5;

    for (int i = tid; i < 128 * 32; i += 512) {
        int rr = i >> 5, c4 = i & 31;
        float4 v = __ldg((const float4*)(W + (size_t)rr * D) + c4);
        *(uint2*)(sh + SM_W + rr * WPITCH + c4 * 8) =
            make_uint2(packh2(v.x, v.y), packh2(v.z, v.w));
    }
    if (tid < D) bsm[tid] = b[tid];

    uint32_t wsh_u = (uint32_t)__cvta_generic_to_shared(sh + SM_W);
    uint32_t x0_u  = (uint32_t)__cvta_generic_to_shared(sh + SM_X0);

    int wm = warp >> 2;
    int wn = warp & 3;
    int n_b = wn * 32;

    int q = lane >> 3;
    int r = lane & 7;
    int g = lane >> 2;
    int t = lane & 3;

    uint32_t bBase = wsh_u + (uint32_t)((n_b + (q >> 1) * 8 + r) * WPITCH + (q & 1) * 16);

    auto issue_x = [&](uint32_t xbuf, int tile) {
        int row0 = tile * 128;
#pragma unroll
        for (int it = 0; it < 8; it++) {
            int idx = it * 512 + tid;
            int rr = idx >> 5, cc = idx & 31;
            int gr = row0 + rr;
            if (gr >= NROWS) gr = NROWS - 1;
            const float* src = X + (size_t)gr * D + cc * 4;
            CP16(xbuf + rr * XPB + cc * 16, src);
        }
    };

    int t0 = blockIdx.x;
    if (t0 < NTILES) issue_x(x0_u, t0);
    asm volatile("cp.async.commit_group;" ::: "memory");
    __syncthreads();

    int bufsel = 0;
    for (int tile = t0; tile < NTILES; tile += 148) {
        uint32_t xcur = bufsel ? (x0_u + XBUFB) : x0_u;
        uint32_t xnxt = bufsel ? x0_u : (x0_u + XBUFB);

        int tn = tile + 148;
        if (tn < NTILES) issue_x(xnxt, tn);
        asm volatile("cp.async.commit_group;" ::: "memory");
        asm volatile("cp.async.wait_group 1;" ::: "memory");
        __syncthreads();

        const float* Xb = (const float*)(sh + (xcur - (uint32_t)__cvta_generic_to_shared(sh)));
        float acc[2][4][4];
#pragma unroll
        for (int mt = 0; mt < 2; mt++)
#pragma unroll
            for (int nt = 0; nt < 4; nt++)
#pragma unroll
                for (int j = 0; j < 4; j++) acc[mt][nt][j] = 0.f;

        int m_b = wm * 32;
#pragma unroll
        for (int ks = 0; ks < 8; ks++) {
            uint32_t A[2][4], B[2][4];
#pragma unroll
            for (int mt = 0; mt < 2; mt++) {
                const float* p0 = Xb + (m_b + mt * 16 + g) * XFP + ks * 16 + 2 * t;
                const float* p1 = p0 + 8 * XFP;
                float2 v0 = *(const float2*)p0;
                float2 v1 = *(const float2*)p1;
                float2 v2 = *(const float2*)(p0 + 8);
                float2 v3 = *(const float2*)(p1 + 8);
                A[mt][0] = packh2(v0.x, v0.y);
                A[mt][1] = packh2(v1.x, v1.y);
                A[mt][2] = packh2(v2.x, v2.y);
                A[mt][3] = packh2(v3.x, v3.y);
            }
#pragma unroll
            for (int np = 0; np < 2; np++)
                LDSM4(B[np], bBase + np * 16 * WPITCH + ks * 32);
#pragma unroll
            for (int mt = 0; mt < 2; mt++)
#pragma unroll
                for (int nt = 0; nt < 4; nt++)
                    MMA16816(acc[mt][nt], A[mt],
                             B[nt >> 1][(nt & 1) * 2], B[nt >> 1][(nt & 1) * 2 + 1]);
        }

        int row0 = tile * 128;
        float tmax = 0.f;
#pragma unroll
        for (int nt = 0; nt < 4; nt++) {
            int col = n_b + nt * 8 + 2 * t;
            float2 bb = *(float2*)(bsm + col);
#pragma unroll
            for (int mt = 0; mt < 2; mt++) {
                int rA = row0 + m_b + mt * 16 + g;
                int rB = rA + 8;
                float e0 = acc[mt][nt][0] + bb.x;
                float e1 = acc[mt][nt][1] + bb.y;
                float e2 = acc[mt][nt][2] + bb.x;
                float e3 = acc[mt][nt][3] + bb.y;
                tmax = fmaxf(tmax, fmaxf(fmaxf(fabsf(e0), fabsf(e1)),
                                         fmaxf(fabsf(e2), fabsf(e3))));
                if (rA < NROWS)
                    *(__half2*)(g_embh + (size_t)rA * D + col) = __floats2half2_rn(e0, e1);
                if (rB < NROWS)
                    *(__half2*)(g_embh + (size_t)rB * D + col) = __floats2half2_rn(e2, e3);
            }
        }
        unsigned um = __reduce_max_sync(0xffffffffu, __float_as_uint(tmax));
        if (lane == 0) atomicMax(&g_gmax_bits, um);

        __syncthreads();
        bufsel ^= 1;
    }
}

// ---------------------------------------------------------------------------
// Kernel 1b: int8 quantization with one GLOBAL scale (streaming convert).
// ---------------------------------------------------------------------------
__global__ void __launch_bounds__(256) quant_kernel() {
    float gmax = __uint_as_float(g_gmax_bits);
    float inv  = 127.f / fmaxf(gmax, 1e-20f);

    size_t idx = (size_t)(blockIdx.x * 256 + threadIdx.x) * 8;
    uint4 v = *(const uint4*)(g_embh + idx);
    const __half2* h2 = (const __half2*)&v;
    int qi[8];
#pragma unroll
    for (int j = 0; j < 4; j++) {
        float2 f = __half22float2(h2[j]);
        qi[2 * j]     = max(-127, min(127, __float2int_rn(f.x * inv)));
        qi[2 * j + 1] = max(-127, min(127, __float2int_rn(f.y * inv)));
    }
    uint32_t p0 = (uint32_t)(qi[0] & 0xFF) | ((uint32_t)(qi[1] & 0xFF) << 8) |
                  ((uint32_t)(qi[2] & 0xFF) << 16) | ((uint32_t)(qi[3] & 0xFF) << 24);
    uint32_t p1 = (uint32_t)(qi[4] & 0xFF) | ((uint32_t)(qi[5] & 0xFF) << 8) |
                  ((uint32_t)(qi[6] & 0xFF) << 16) | ((uint32_t)(qi[7] & 0xFF) << 24);
    *(uint2*)(g_embi8 + idx) = make_uint2(p0, p1);
}

// ---------------------------------------------------------------------------
// Kernel 2: WARP-PER-PAIR with cp.async gather pipeline (depth-4 smem ring).
// Each lane cp.asyncs its own 16B of a row; wait_group orders the lane's own
// readback, so no intra-loop syncs. In-flight gathers: ~40 warps x 12 rows
// per SM (~5x the register-LDG ceiling that pinned R10-R13 at ~93us).
// ---------------------------------------------------------------------------
#define BR_DEPTH 4

__global__ void __launch_bounds__(256) branch_kernel(
                              const int* __restrict__ pos_anchor,
                              const int* __restrict__ pos_partner,
                              const int* __restrict__ neg_idx,
                              const int* __restrict__ weak_anchor,
                              const int* __restrict__ weak_partner,
                              const int* __restrict__ weak_neg_idx) {
    __shared__ int sidx[8][NEG];                         // 8 KB
    __shared__ __align__(16) int8_t ring[8][BR_DEPTH][512];   // 16 KB

    int tid  = threadIdx.x;
    int lane = tid & 31;
    int warp = tid >> 5;

    int p  = blockIdx.x * 8 + warp;
    int br = blockIdx.y;
    const int* anc = br ? weak_anchor  : pos_anchor;
    const int* par = br ? weak_partner : pos_partner;
    const int* nix = br ? weak_neg_idx : neg_idx;

    int a  = anc[p];                // warp-broadcast loads
    int pr = par[p];

    // stage this warp's 256 indices (2x LDG.128 per lane)
    {
        const int4* np4 = (const int4*)(nix + (size_t)p * NEG);
        int4 i0 = np4[lane];
        int4 i1 = np4[lane + 32];
        ((int4*)sidx[warp])[lane]      = i0;
        ((int4*)sidx[warp])[lane + 32] = i1;
    }

    // q int8 row -> per-lane 16B chunk via shfl
    int gl  = lane & 7;             // lane within 8-lane row group
    int grp = lane >> 3;            // which negative of the quad
    uint32_t qrow = ((const uint32_t*)(g_embi8 + (size_t)a * D))[lane];
    uint32_t qp[4];
#pragma unroll
    for (int j = 0; j < 4; j++)
        qp[j] = __shfl_sync(0xffffffffu, qrow, gl * 4 + j);

    // positive dot (fp16-accuracy path): 4 halves per lane
    float pos;
    {
        uint2 qh = ((const uint2*)(g_embh + (size_t)a  * D))[lane];
        uint2 kh = ((const uint2*)(g_embh + (size_t)pr * D))[lane];
        __half2 q0 = *(__half2*)&qh.x, q1 = *(__half2*)&qh.y;
        __half2 k0 = *(__half2*)&kh.x, k1 = *(__half2*)&kh.y;
        float2 fq0 = __half22float2(q0), fq1 = __half22float2(q1);
        float2 fk0 = __half22float2(k0), fk1 = __half22float2(k1);
        float s = fq0.x * fk0.x + fq0.y * fk0.y + fq1.x * fk1.x + fq1.y * fk1.y;
#pragma unroll
        for (int m = 16; m >= 1; m >>= 1) s += __shfl_xor_sync(0xffffffffu, s, m);
        pos = s;
    }

    float gmax = __uint_as_float(g_gmax_bits);
    float gsc  = gmax * (1.f / 127.f);
    float gs2  = gsc * gsc;

    __syncwarp();                   // sidx visible across the warp

    uint32_t gmask = 0xFFu << (grp * 8);
    const int8_t* gbase = g_embi8 + (gl << 4);
    const int* sw = sidx[warp] + grp;
    uint32_t ring_u = (uint32_t)__cvta_generic_to_shared(ring[warp]) + lane * 16;
    const int8_t* ringp = &ring[warp][0][0] + lane * 16;

    // prologue: fill pipeline (slots 0..BR_DEPTH-2), one commit per slot
#pragma unroll
    for (int it = 0; it < BR_DEPTH - 1; it++) {
        int idx = sw[it * 4];
        CP16(ring_u + (uint32_t)(it << 9), gbase + ((size_t)idx << 7));
        asm volatile("cp.async.commit_group;" ::: "memory");
    }

    float dots[8];
#pragma unroll
    for (int it = 0; it < 64; it++) {
        // issue it+DEPTH-1 (or empty commit to keep group accounting constant)
        if (it < 64 - (BR_DEPTH - 1)) {
            int nidx = sw[(it + BR_DEPTH - 1) * 4];
            CP16(ring_u + (uint32_t)(((it + BR_DEPTH - 1) & (BR_DEPTH - 1)) << 9),
                 gbase + ((size_t)nidx << 7));
        }
        asm volatile("cp.async.commit_group;" ::: "memory");
        asm volatile("cp.async.wait_group %0;" :: "n"(BR_DEPTH - 1) : "memory");

        uint4 v = *(const uint4*)(ringp + ((it & (BR_DEPTH - 1)) << 9));
        int isum = 0;
        isum = __dp4a((int)v.x, (int)qp[0], isum);
        isum = __dp4a((int)v.y, (int)qp[1], isum);
        isum = __dp4a((int)v.z, (int)qp[2], isum);
        isum = __dp4a((int)v.w, (int)qp[3], isum);
        isum = __reduce_add_sync(gmask, isum);
        if ((it & 7) == gl) dots[it >> 3] = (float)isum * gs2;
    }

    // warp-local logsumexp over 257 logits
    const float invT = 1.0f / TEMPF;
    float mv = pos;
#pragma unroll
    for (int k = 0; k < 8; k++) mv = fmaxf(mv, dots[k]);
#pragma unroll
    for (int m = 16; m >= 1; m >>= 1) mv = fmaxf(mv, __shfl_xor_sync(0xffffffffu, mv, m));
    float ml = mv * invT;

    float e = 0.f;
#pragma unroll
    for (int k = 0; k < 8; k++) e += __expf(dots[k] * invT - ml);
#pragma unroll
    for (int m = 16; m >= 1; m >>= 1) e += __shfl_xor_sync(0xffffffffu, e, m);

    if (lane == 0) {
        float total = e + __expf(pos * invT - ml);
        g_losses[br * PP + p] = ml + __logf(total) - pos * invT;
    }
}

// ---------------------------------------------------------------------------
// Kernel 3: deterministic mean reduction (1024 threads, MLP-overlapped)
// ---------------------------------------------------------------------------
__global__ void __launch_bounds__(1024) finalize_kernel(float* __restrict__ out) {
    __shared__ double s0sh[1024], s1sh[1024];
    int tid = threadIdx.x;
    double s0 = 0.0, s1 = 0.0;
#pragma unroll
    for (int i = 0; i < PP / 1024; i++) {
        s0 += (double)g_losses[i * 1024 + tid];
        s1 += (double)g_losses[PP + i * 1024 + tid];
    }
    s0sh[tid] = s0; s1sh[tid] = s1;
    __syncthreads();
    for (int st = 512; st > 0; st >>= 1) {
        if (tid < st) { s0sh[tid] += s0sh[tid + st]; s1sh[tid] += s1sh[tid + st]; }
        __syncthreads();
    }
    if (tid == 0)
        out[0] = (float)(s0sh[0] / (double)PP + 0.1 * (s1sh[0] / (double)PP));
}

extern "C" void kernel_launch(void* const* d_in, const int* in_sizes, int n_in,
                              void* d_out, int out_size) {
    const float* X  = (const float*)d_in[0];
    const float* W  = (const float*)d_in[1];
    const float* b  = (const float*)d_in[2];
    const int*   pa = (const int*)d_in[3];
    const int*   pp = (const int*)d_in[4];
    const int*   ni = (const int*)d_in[5];
    const int*   wa = (const int*)d_in[6];
    const int*   wp = (const int*)d_in[7];
    const int*   wn = (const int*)d_in[8];
    float* out = (float*)d_out;

    cudaFuncSetAttribute(gemm_kernel, cudaFuncAttributeMaxDynamicSharedMemorySize, GEMM_SMEM);

    init_kernel<<<1, 1>>>();
    gemm_kernel<<<148, 512, GEMM_SMEM>>>(X, W, b);
    quant_kernel<<<(NROWS * D / 8) / 256, 256>>>();   // 6250 blocks exact
    branch_kernel<<<dim3(PP / 8, 2), 256>>>(pa, pp, ni, wa, wp, wn);
    finalize_kernel<<<1, 1024>>>(out);
}